// round 2
// baseline (speedup 1.0000x reference)
#include <cuda_runtime.h>

#define PKE 134217728   // 4096*8*64*64 elements of p_k / p_v / out

// Scratch (allocation-free rule: __device__ globals)
__device__ float g_q[PKE];    // q in [B,H,N,hd] layout, pre-scaled
__device__ float g_ao[PKE];   // attention output in [B,N,H*hd] layout

// ---------------------------------------------------------------------------
// SGEMM NT: C = A(Mx512) * W(512x512)^T + bias
// MODE 0: write to q layout [B,H,N,64] with *0.125 scale
// MODE 1: write row-major [M,512]
// ---------------------------------------------------------------------------
template <int MODE>
__global__ void __launch_bounds__(256, 2) sgemm_nt(
    const float* __restrict__ A, const float* __restrict__ W,
    const float* __restrict__ bias, float* __restrict__ C)
{
    __shared__ float As[16][128];
    __shared__ float Bs[16][128];

    const int tid  = threadIdx.x;
    const int m0   = blockIdx.y * 128;
    const int n0   = blockIdx.x * 128;
    const int tx   = tid & 15;        // micro-tile col group
    const int ty   = tid >> 4;        // micro-tile row group
    const int lrow = tid >> 2;        // 0..63, load row
    const int kq   = (tid & 3) << 2;  // 0,4,8,12 within BK

    const float* Ap = A + (m0 + lrow) * 512 + kq;
    const float* Wp = W + (n0 + lrow) * 512 + kq;

    float acc[8][8];
#pragma unroll
    for (int r = 0; r < 8; r++)
#pragma unroll
        for (int c = 0; c < 8; c++) acc[r][c] = 0.f;

    for (int kt = 0; kt < 512; kt += 16) {
        float4 a0 = *(const float4*)(Ap + kt);
        float4 a1 = *(const float4*)(Ap + 64 * 512 + kt);
        float4 b0 = *(const float4*)(Wp + kt);
        float4 b1 = *(const float4*)(Wp + 64 * 512 + kt);
        __syncthreads();
        As[kq + 0][lrow] = a0.x; As[kq + 1][lrow] = a0.y;
        As[kq + 2][lrow] = a0.z; As[kq + 3][lrow] = a0.w;
        As[kq + 0][lrow + 64] = a1.x; As[kq + 1][lrow + 64] = a1.y;
        As[kq + 2][lrow + 64] = a1.z; As[kq + 3][lrow + 64] = a1.w;
        Bs[kq + 0][lrow] = b0.x; Bs[kq + 1][lrow] = b0.y;
        Bs[kq + 2][lrow] = b0.z; Bs[kq + 3][lrow] = b0.w;
        Bs[kq + 0][lrow + 64] = b1.x; Bs[kq + 1][lrow + 64] = b1.y;
        Bs[kq + 2][lrow + 64] = b1.z; Bs[kq + 3][lrow + 64] = b1.w;
        __syncthreads();
#pragma unroll
        for (int k = 0; k < 16; k++) {
            float4 af0 = *(const float4*)&As[k][ty * 8];
            float4 af1 = *(const float4*)&As[k][ty * 8 + 4];
            float4 bf0 = *(const float4*)&Bs[k][tx * 8];
            float4 bf1 = *(const float4*)&Bs[k][tx * 8 + 4];
            float a_[8] = {af0.x, af0.y, af0.z, af0.w, af1.x, af1.y, af1.z, af1.w};
            float b_[8] = {bf0.x, bf0.y, bf0.z, bf0.w, bf1.x, bf1.y, bf1.z, bf1.w};
#pragma unroll
            for (int r = 0; r < 8; r++)
#pragma unroll
                for (int c = 0; c < 8; c++)
                    acc[r][c] += a_[r] * b_[c];
        }
    }

    float4 bv0 = *(const float4*)(bias + n0 + tx * 8);
    float4 bv1 = *(const float4*)(bias + n0 + tx * 8 + 4);
    float bb[8] = {bv0.x, bv0.y, bv0.z, bv0.w, bv1.x, bv1.y, bv1.z, bv1.w};

#pragma unroll
    for (int r = 0; r < 8; r++) {
        int mrow = m0 + ty * 8 + r;
        int jc   = n0 + tx * 8;
        if (MODE == 0) {
            const float s = 0.125f;   // hd^-0.5, hd=64
            int b_i = mrow >> 6, n_i = mrow & 63;
            int h_i = jc >> 6,  d_i = jc & 63;
            int o = (((b_i << 3) + h_i) << 12) + (n_i << 6) + d_i;
            float4 o0 = make_float4((acc[r][0] + bb[0]) * s, (acc[r][1] + bb[1]) * s,
                                    (acc[r][2] + bb[2]) * s, (acc[r][3] + bb[3]) * s);
            float4 o1 = make_float4((acc[r][4] + bb[4]) * s, (acc[r][5] + bb[5]) * s,
                                    (acc[r][6] + bb[6]) * s, (acc[r][7] + bb[7]) * s);
            *(float4*)&C[o]     = o0;
            *(float4*)&C[o + 4] = o1;
        } else {
            int o = mrow * 512 + jc;
            float4 o0 = make_float4(acc[r][0] + bb[0], acc[r][1] + bb[1],
                                    acc[r][2] + bb[2], acc[r][3] + bb[3]);
            float4 o1 = make_float4(acc[r][4] + bb[4], acc[r][5] + bb[5],
                                    acc[r][6] + bb[6], acc[r][7] + bb[7]);
            *(float4*)&C[o]     = o0;
            *(float4*)&C[o + 4] = o1;
        }
    }
}

// ---------------------------------------------------------------------------
// Attention: one block per (window b, head h). 64x64 tiles in smem.
// S = Q K^T + bias + mask ; P = softmax(S) ; O = P V  -> g_ao [B,N,H*64]
// ---------------------------------------------------------------------------
__global__ void __launch_bounds__(256) attn_kernel(
    const float* __restrict__ pk, const float* __restrict__ pv,
    const float* __restrict__ mask, const float* __restrict__ table,
    const int* __restrict__ rpi)
{
    extern __shared__ float smf[];
    float* Qt = smf;           // [64 d][64 i]  (d-major)
    float* Kt = smf + 4096;    // [64 d][64 j]
    float* Vs = smf + 8192;    // [64 j][64 d]  (natural)
    float* Ss = smf;           // [64][65], overlays dead Qt/Kt after S-GEMM

    const int tid = threadIdx.x;
    const int bh  = blockIdx.x;
    const int b   = bh >> 3, h = bh & 7;
    const int w   = b & 255;   // window index within image (NW=256)

    const float* qg = g_q + (size_t)bh * 4096;
    const float* kg = pk  + (size_t)bh * 4096;
    const float* vg = pv  + (size_t)bh * 4096;

    // Fill V (direct copy) and Q/K (transpose to d-major)
    for (int f = tid; f < 1024; f += 256)
        ((float4*)Vs)[f] = ((const float4*)vg)[f];

    const int i_ = tid >> 2;
#pragma unroll
    for (int r = 0; r < 4; r++) {
        int dq = ((tid & 3) << 2) + r;          // float4 index within row
        float4 q4 = ((const float4*)qg)[i_ * 16 + dq];
        float4 k4 = ((const float4*)kg)[i_ * 16 + dq];
        int d0 = dq << 2;
        Qt[(d0 + 0) * 64 + i_] = q4.x; Qt[(d0 + 1) * 64 + i_] = q4.y;
        Qt[(d0 + 2) * 64 + i_] = q4.z; Qt[(d0 + 3) * 64 + i_] = q4.w;
        Kt[(d0 + 0) * 64 + i_] = k4.x; Kt[(d0 + 1) * 64 + i_] = k4.y;
        Kt[(d0 + 2) * 64 + i_] = k4.z; Kt[(d0 + 3) * 64 + i_] = k4.w;
    }
    __syncthreads();

    // S = Q K^T : 4x4 micro-tile per thread, 16x16 thread grid
    const int tj = tid & 15, ti = tid >> 4;
    float sacc[4][4];
#pragma unroll
    for (int r = 0; r < 4; r++)
#pragma unroll
        for (int c = 0; c < 4; c++) sacc[r][c] = 0.f;

#pragma unroll 16
    for (int d = 0; d < 64; d++) {
        float4 qa = *(const float4*)&Qt[d * 64 + ti * 4];
        float4 kb = *(const float4*)&Kt[d * 64 + tj * 4];
        float a_[4] = {qa.x, qa.y, qa.z, qa.w};
        float b_[4] = {kb.x, kb.y, kb.z, kb.w};
#pragma unroll
        for (int r = 0; r < 4; r++)
#pragma unroll
            for (int c = 0; c < 4; c++)
                sacc[r][c] += a_[r] * b_[c];
    }
    __syncthreads();   // all Qt/Kt reads complete before Ss overlay writes

    const float* mrow_ = mask + (size_t)w * 4096;
#pragma unroll
    for (int r = 0; r < 4; r++) {
        int i = ti * 4 + r;
#pragma unroll
        for (int c = 0; c < 4; c++) {
            int j = tj * 4 + c;
            int rp = rpi[i * 64 + j];
            Ss[i * 65 + j] = sacc[r][c] + table[rp * 8 + h] + mrow_[i * 64 + j];
        }
    }
    __syncthreads();

    // Row softmax: 4 threads per row (quad-aligned for shfl_xor 1,2)
    {
        const int rr = tid >> 2, q4l = tid & 3;
        float* srow = Ss + rr * 65 + q4l * 16;
        float mx = -1e30f;
#pragma unroll
        for (int jj = 0; jj < 16; jj++) mx = fmaxf(mx, srow[jj]);
        mx = fmaxf(mx, __shfl_xor_sync(0xffffffffu, mx, 1));
        mx = fmaxf(mx, __shfl_xor_sync(0xffffffffu, mx, 2));
        float e[16];
        float sum = 0.f;
#pragma unroll
        for (int jj = 0; jj < 16; jj++) { e[jj] = __expf(srow[jj] - mx); sum += e[jj]; }
        sum += __shfl_xor_sync(0xffffffffu, sum, 1);
        sum += __shfl_xor_sync(0xffffffffu, sum, 2);
        float inv = 1.0f / sum;
#pragma unroll
        for (int jj = 0; jj < 16; jj++) srow[jj] = e[jj] * inv;
    }
    __syncthreads();

    // O = P V : 4x4 micro-tile per thread over (i, d)
    const int td = tid & 15, ti2 = tid >> 4;
    float oacc[4][4];
#pragma unroll
    for (int r = 0; r < 4; r++)
#pragma unroll
        for (int c = 0; c < 4; c++) oacc[r][c] = 0.f;

#pragma unroll 8
    for (int j = 0; j < 64; j++) {
        float4 vb = *(const float4*)&Vs[j * 64 + td * 4];
        float v_[4] = {vb.x, vb.y, vb.z, vb.w};
#pragma unroll
        for (int r = 0; r < 4; r++) {
            float p = Ss[(ti2 * 4 + r) * 65 + j];
#pragma unroll
            for (int c = 0; c < 4; c++)
                oacc[r][c] += p * v_[c];
        }
    }

    float* og = g_ao + (size_t)(b * 64) * 512 + h * 64;
#pragma unroll
    for (int r = 0; r < 4; r++) {
        int i = ti2 * 4 + r;
        *(float4*)&og[(size_t)i * 512 + td * 4] =
            make_float4(oacc[r][0], oacc[r][1], oacc[r][2], oacc[r][3]);
    }
}

// ---------------------------------------------------------------------------
extern "C" void kernel_launch(void* const* d_in, const int* in_sizes, int n_in,
                              void* d_out, int out_size)
{
    const float* x      = (const float*)d_in[0];
    const float* pk     = (const float*)d_in[1];
    const float* pv     = (const float*)d_in[2];
    const float* mask   = (const float*)d_in[3];
    const float* table  = (const float*)d_in[4];
    const int*   rpi    = (const int*)d_in[5];
    const float* qkv_w  = (const float*)d_in[6];
    const float* qkv_b  = (const float*)d_in[7];
    const float* proj_w = (const float*)d_in[8];
    const float* proj_b = (const float*)d_in[9];
    float* out = (float*)d_out;

    // Pass-through outputs: (out, p_k, p_v) tuple concat
    cudaMemcpyAsync(out + (size_t)PKE,     pk, (size_t)PKE * sizeof(float),
                    cudaMemcpyDeviceToDevice, 0);
    cudaMemcpyAsync(out + (size_t)2 * PKE, pv, (size_t)PKE * sizeof(float),
                    cudaMemcpyDeviceToDevice, 0);

    float *qbuf, *aobuf;
    cudaGetSymbolAddress((void**)&qbuf, g_q);
    cudaGetSymbolAddress((void**)&aobuf, g_ao);

    dim3 ggrid(4, 2048);   // N/128 x M/128
    sgemm_nt<0><<<ggrid, 256>>>(x, qkv_w, qkv_b, qbuf);

    attn_kernel<<<32768, 256, 49152>>>(pk, pv, mask, table, rpi);

    sgemm_nt<1><<<ggrid, 256>>>(aobuf, proj_w, proj_b, out);
}

// round 4
// speedup vs baseline: 1.7284x; 1.7284x over previous
#include <cuda_runtime.h>
#include <cuda_bf16.h>
#include <cstdint>

#define PKE 134217728   // 4096*8*64*64

// Scratch (__device__ globals; allocation-free rule)
__device__ float g_q[PKE];                   // q in [B,H,N,64], pre-scaled
__device__ float g_ao[PKE];                  // attention out [B*N, 512] fp32
__device__ __nv_bfloat16 g_wh[2][262144];    // weight hi: [0]=qkv_w, [1]=proj_w
__device__ __nv_bfloat16 g_wl[2][262144];    // weight lo

// ---------------------------------------------------------------------------
// helpers
// ---------------------------------------------------------------------------
__device__ __forceinline__ uint32_t smem_u32(const void* p) {
    uint32_t a;
    asm("{ .reg .u64 t; cvta.to.shared.u64 t, %1; cvt.u32.u64 %0, t; }"
        : "=r"(a) : "l"(p));
    return a;
}

__device__ __forceinline__ void ldsm_x4(uint32_t* d, uint32_t addr) {
    asm volatile("ldmatrix.sync.aligned.m8n8.x4.shared.b16 {%0,%1,%2,%3}, [%4];"
        : "=r"(d[0]), "=r"(d[1]), "=r"(d[2]), "=r"(d[3]) : "r"(addr));
}

__device__ __forceinline__ void mma16816(float* c, const uint32_t* a,
                                         uint32_t b0, uint32_t b1) {
    asm volatile("mma.sync.aligned.m16n8k16.row.col.f32.bf16.bf16.f32 "
        "{%0,%1,%2,%3}, {%4,%5,%6,%7}, {%8,%9}, {%0,%1,%2,%3};"
        : "+f"(c[0]), "+f"(c[1]), "+f"(c[2]), "+f"(c[3])
        : "r"(a[0]), "r"(a[1]), "r"(a[2]), "r"(a[3]), "r"(b0), "r"(b1));
}

__device__ __forceinline__ uint32_t pack_bf2(float a, float b) {
    __nv_bfloat162 t = __floats2bfloat162_rn(a, b);
    return *reinterpret_cast<uint32_t*>(&t);
}

// ---------------------------------------------------------------------------
// Weight fp32 -> bf16 hi/lo split
// ---------------------------------------------------------------------------
__global__ void conv_w_kernel(const float* __restrict__ w0, const float* __restrict__ w1)
{
    int which = blockIdx.y;
    const float* src = which ? w1 : w0;
    int i = blockIdx.x * 256 + threadIdx.x;          // float4 index, 65536 total
    float4 v = ((const float4*)src)[i];
    __nv_bfloat16 hx = __float2bfloat16(v.x), hy = __float2bfloat16(v.y);
    __nv_bfloat16 hz = __float2bfloat16(v.z), hw = __float2bfloat16(v.w);
    float lx = v.x - __bfloat162float(hx), ly = v.y - __bfloat162float(hy);
    float lz = v.z - __bfloat162float(hz), lw = v.w - __bfloat162float(hw);
    uint2 h = make_uint2(pack_bf2(__bfloat162float(hx), __bfloat162float(hy)),
                         pack_bf2(__bfloat162float(hz), __bfloat162float(hw)));
    uint2 l = make_uint2(pack_bf2(lx, ly), pack_bf2(lz, lw));
    ((uint2*)g_wh[which])[i] = h;
    ((uint2*)g_wl[which])[i] = l;
}

// ---------------------------------------------------------------------------
// mma.sync split-bf16 GEMM:  C[M,512] = A[M,512](fp32) * W[512,512]^T + bias
// CTA tile 128x128, K-chunk 32, double-buffered smem, 8 warps (4 m x 2 n).
// smem rows padded to 80B for conflict-free ldmatrix.
// MODE 0: write q layout [B,H,N,64] * 0.125 ; MODE 1: row-major [M,512]
// ---------------------------------------------------------------------------
#define RP     80                     // smem row pitch (bytes) for 32 bf16
#define AH_OFF 0
#define AL_OFF 10240
#define WH_OFF 20480
#define WL_OFF 30720
#define G_STAGE 40960
#define G_SMEM  (2 * G_STAGE)         // 81920

template <int MODE>
__global__ void __launch_bounds__(256) gemm_mma(
    const float* __restrict__ A, const __nv_bfloat16* __restrict__ Wh,
    const __nv_bfloat16* __restrict__ Wl, const float* __restrict__ bias,
    float* __restrict__ C)
{
    extern __shared__ char smem[];
    const uint32_t sbase = smem_u32(smem);
    const int tid  = threadIdx.x;
    const int wid  = tid >> 5;
    const int lane = tid & 31;
    const int wr   = wid & 3;          // warp m: 32 rows
    const int wn   = wid >> 2;         // warp n: 64 cols
    const int n0   = blockIdx.x;       // 0..3   (N tile of 128)
    const int m0   = blockIdx.y;       // 0..2047

    // lane-dependent ldmatrix address components
    const int L = lane;
    const uint32_t a_lrow = (L & 7) + ((L >> 3) & 1) * 8;       // + mt*16
    const uint32_t a_lcol = ((L >> 4) & 1) * 16;                // + s*32
    const uint32_t b_lrow = (L & 7) + ((L >> 4) & 1) * 8;       // + g*16
    const uint32_t b_lcol = ((L >> 3) & 1) * 16;                // + s*32

    float acc[2][8][4];
#pragma unroll
    for (int mt = 0; mt < 2; mt++)
#pragma unroll
        for (int nt = 0; nt < 8; nt++)
#pragma unroll
            for (int q = 0; q < 4; q++) acc[mt][nt][q] = 0.f;

    float4 areg[4];
    uint4  whreg[2], wlreg[2];

    // ---- staging lambdas (macros via code blocks) ----
#define LDG_CHUNK(kt)                                                          \
    {                                                                          \
        _Pragma("unroll")                                                      \
        for (int i = 0; i < 4; i++) {                                          \
            int cid = tid + i * 256;                                           \
            int r = cid >> 3, c4 = cid & 7;                                    \
            areg[i] = ((const float4*)A)[(size_t)(m0 * 128 + r) * 128 + (kt) * 8 + c4]; \
        }                                                                      \
        _Pragma("unroll")                                                      \
        for (int i = 0; i < 2; i++) {                                          \
            int cid = tid + i * 256;                                           \
            int r = cid >> 2, cu = cid & 3;                                    \
            size_t gi = (size_t)(n0 * 128 + r) * 64 + (kt) * 4 + cu;           \
            whreg[i] = ((const uint4*)Wh)[gi];                                 \
            wlreg[i] = ((const uint4*)Wl)[gi];                                 \
        }                                                                      \
    }

#define STS_CHUNK(buf)                                                         \
    {                                                                          \
        char* stg = smem + (buf) * G_STAGE;                                    \
        _Pragma("unroll")                                                      \
        for (int i = 0; i < 4; i++) {                                          \
            int cid = tid + i * 256;                                           \
            int r = cid >> 3, c4 = cid & 7;                                    \
            uint32_t off = r * RP + c4 * 8;                                    \
            float4 v = areg[i];                                                \
            __nv_bfloat16 hx = __float2bfloat16(v.x), hy = __float2bfloat16(v.y); \
            __nv_bfloat16 hz = __float2bfloat16(v.z), hw = __float2bfloat16(v.w); \
            float lx = v.x - __bfloat162float(hx), ly = v.y - __bfloat162float(hy); \
            float lz = v.z - __bfloat162float(hz), lw = v.w - __bfloat162float(hw); \
            *(uint2*)(stg + AH_OFF + off) =                                    \
                make_uint2(pack_bf2(__bfloat162float(hx), __bfloat162float(hy)), \
                           pack_bf2(__bfloat162float(hz), __bfloat162float(hw))); \
            *(uint2*)(stg + AL_OFF + off) =                                    \
                make_uint2(pack_bf2(lx, ly), pack_bf2(lz, lw));                \
        }                                                                      \
        _Pragma("unroll")                                                      \
        for (int i = 0; i < 2; i++) {                                          \
            int cid = tid + i * 256;                                           \
            int r = cid >> 2, cu = cid & 3;                                    \
            uint32_t off = r * RP + cu * 16;                                   \
            *(uint4*)(stg + WH_OFF + off) = whreg[i];                          \
            *(uint4*)(stg + WL_OFF + off) = wlreg[i];                          \
        }                                                                      \
    }

    LDG_CHUNK(0);
    STS_CHUNK(0);
    LDG_CHUNK(1);
    __syncthreads();

    for (int kt = 0; kt < 16; kt++) {
        const int b = kt & 1;
        if (kt < 15) STS_CHUNK(1 - b);
        if (kt < 14) LDG_CHUNK(kt + 2);
        __syncthreads();

        const uint32_t stg = sbase + b * G_STAGE;
#pragma unroll
        for (int s = 0; s < 2; s++) {
            uint32_t ah[2][4], al[2][4];
#pragma unroll
            for (int mt = 0; mt < 2; mt++) {
                uint32_t ro = (wr * 32 + mt * 16 + a_lrow) * RP + s * 32 + a_lcol;
                ldsm_x4(ah[mt], stg + AH_OFF + ro);
                ldsm_x4(al[mt], stg + AL_OFF + ro);
            }
#pragma unroll
            for (int g = 0; g < 4; g++) {
                uint32_t bh[4], bl[4];
                uint32_t ro = (wn * 64 + g * 16 + b_lrow) * RP + s * 32 + b_lcol;
                ldsm_x4(bh, stg + WH_OFF + ro);
                ldsm_x4(bl, stg + WL_OFF + ro);
#pragma unroll
                for (int mt = 0; mt < 2; mt++) {
                    mma16816(acc[mt][2 * g],     ah[mt], bh[0], bh[1]);
                    mma16816(acc[mt][2 * g + 1], ah[mt], bh[2], bh[3]);
                    mma16816(acc[mt][2 * g],     al[mt], bh[0], bh[1]);
                    mma16816(acc[mt][2 * g + 1], al[mt], bh[2], bh[3]);
                    mma16816(acc[mt][2 * g],     ah[mt], bl[0], bl[1]);
                    mma16816(acc[mt][2 * g + 1], ah[mt], bl[2], bl[3]);
                }
            }
        }
        __syncthreads();
    }

    // ---- epilogue ----
    const int g_  = lane >> 2;
    const int tig = lane & 3;
#pragma unroll
    for (int mt = 0; mt < 2; mt++) {
        const int mbase = m0 * 128 + wr * 32 + mt * 16 + g_;
#pragma unroll
        for (int nt = 0; nt < 8; nt++) {
            const int j = n0 * 128 + wn * 64 + nt * 8 + tig * 2;
            const float bx = __ldg(bias + j), by = __ldg(bias + j + 1);
#pragma unroll
            for (int half = 0; half < 2; half++) {
                const int m = mbase + half * 8;
                float ox = acc[mt][nt][2 * half]     + bx;
                float oy = acc[mt][nt][2 * half + 1] + by;
                float* dst;
                if (MODE == 0) {
                    ox *= 0.125f; oy *= 0.125f;
                    int b_i = m >> 6, n_i = m & 63;
                    int h_i = j >> 6, d_i = j & 63;
                    dst = C + (((size_t)(b_i * 8 + h_i)) << 12) + (n_i << 6) + d_i;
                } else {
                    dst = C + (size_t)m * 512 + j;
                }
                *(float2*)dst = make_float2(ox, oy);
            }
        }
    }
#undef LDG_CHUNK
#undef STS_CHUNK
}

// ---------------------------------------------------------------------------
// Attention: one block per (window b, head h). 64x64 tiles in smem.
// ---------------------------------------------------------------------------
__global__ void __launch_bounds__(256) attn_kernel(
    const float* __restrict__ pk, const float* __restrict__ pv,
    const float* __restrict__ mask, const float* __restrict__ table,
    const int* __restrict__ rpi)
{
    extern __shared__ float smf[];
    float* Qt = smf;           // [64 d][64 i]
    float* Kt = smf + 4096;    // [64 d][64 j]
    float* Vs = smf + 8192;    // [64 j][64 d]
    float* Ss = smf;           // [64][65], overlays Qt/Kt

    const int tid = threadIdx.x;
    const int bh  = blockIdx.x;
    const int b   = bh >> 3, h = bh & 7;
    const int w   = b & 255;

    const float* qg = g_q + (size_t)bh * 4096;
    const float* kg = pk  + (size_t)bh * 4096;
    const float* vg = pv  + (size_t)bh * 4096;

    for (int f = tid; f < 1024; f += 256)
        ((float4*)Vs)[f] = ((const float4*)vg)[f];

    const int i_ = tid >> 2;
#pragma unroll
    for (int r = 0; r < 4; r++) {
        int dq = ((tid & 3) << 2) + r;
        float4 q4 = ((const float4*)qg)[i_ * 16 + dq];
        float4 k4 = ((const float4*)kg)[i_ * 16 + dq];
        int d0 = dq << 2;
        Qt[(d0 + 0) * 64 + i_] = q4.x; Qt[(d0 + 1) * 64 + i_] = q4.y;
        Qt[(d0 + 2) * 64 + i_] = q4.z; Qt[(d0 + 3) * 64 + i_] = q4.w;
        Kt[(d0 + 0) * 64 + i_] = k4.x; Kt[(d0 + 1) * 64 + i_] = k4.y;
        Kt[(d0 + 2) * 64 + i_] = k4.z; Kt[(d0 + 3) * 64 + i_] = k4.w;
    }
    __syncthreads();

    const int tj = tid & 15, ti = tid >> 4;
    float sacc[4][4];
#pragma unroll
    for (int r = 0; r < 4; r++)
#pragma unroll
        for (int c = 0; c < 4; c++) sacc[r][c] = 0.f;

#pragma unroll 16
    for (int d = 0; d < 64; d++) {
        float4 qa = *(const float4*)&Qt[d * 64 + ti * 4];
        float4 kb = *(const float4*)&Kt[d * 64 + tj * 4];
        float a_[4] = {qa.x, qa.y, qa.z, qa.w};
        float b_[4] = {kb.x, kb.y, kb.z, kb.w};
#pragma unroll
        for (int r = 0; r < 4; r++)
#pragma unroll
            for (int c = 0; c < 4; c++)
                sacc[r][c] += a_[r] * b_[c];
    }
    __syncthreads();

    const float* mrow_ = mask + (size_t)w * 4096;
#pragma unroll
    for (int r = 0; r < 4; r++) {
        int i = ti * 4 + r;
#pragma unroll
        for (int c = 0; c < 4; c++) {
            int j = tj * 4 + c;
            int rp = rpi[i * 64 + j];
            Ss[i * 65 + j] = sacc[r][c] + table[rp * 8 + h] + mrow_[i * 64 + j];
        }
    }
    __syncthreads();

    {
        const int rr = tid >> 2, q4l = tid & 3;
        float* srow = Ss + rr * 65 + q4l * 16;
        float mx = -1e30f;
#pragma unroll
        for (int jj = 0; jj < 16; jj++) mx = fmaxf(mx, srow[jj]);
        mx = fmaxf(mx, __shfl_xor_sync(0xffffffffu, mx, 1));
        mx = fmaxf(mx, __shfl_xor_sync(0xffffffffu, mx, 2));
        float e[16];
        float sum = 0.f;
#pragma unroll
        for (int jj = 0; jj < 16; jj++) { e[jj] = __expf(srow[jj] - mx); sum += e[jj]; }
        sum += __shfl_xor_sync(0xffffffffu, sum, 1);
        sum += __shfl_xor_sync(0xffffffffu, sum, 2);
        float inv = 1.0f / sum;
#pragma unroll
        for (int jj = 0; jj < 16; jj++) srow[jj] = e[jj] * inv;
    }
    __syncthreads();

    const int td = tid & 15, ti2 = tid >> 4;
    float oacc[4][4];
#pragma unroll
    for (int r = 0; r < 4; r++)
#pragma unroll
        for (int c = 0; c < 4; c++) oacc[r][c] = 0.f;

#pragma unroll 8
    for (int j = 0; j < 64; j++) {
        float4 vb = *(const float4*)&Vs[j * 64 + td * 4];
        float v_[4] = {vb.x, vb.y, vb.z, vb.w};
#pragma unroll
        for (int r = 0; r < 4; r++) {
            float p = Ss[(ti2 * 4 + r) * 65 + j];
#pragma unroll
            for (int c = 0; c < 4; c++)
                oacc[r][c] += p * v_[c];
        }
    }

    float* og = g_ao + (size_t)(b * 64) * 512 + h * 64;
#pragma unroll
    for (int r = 0; r < 4; r++) {
        int i = ti2 * 4 + r;
        *(float4*)&og[(size_t)i * 512 + td * 4] =
            make_float4(oacc[r][0], oacc[r][1], oacc[r][2], oacc[r][3]);
    }
}

// ---------------------------------------------------------------------------
extern "C" void kernel_launch(void* const* d_in, const int* in_sizes, int n_in,
                              void* d_out, int out_size)
{
    const float* x      = (const float*)d_in[0];
    const float* pk     = (const float*)d_in[1];
    const float* pv     = (const float*)d_in[2];
    const float* mask   = (const float*)d_in[3];
    const float* table  = (const float*)d_in[4];
    const int*   rpi    = (const int*)d_in[5];
    const float* qkv_w  = (const float*)d_in[6];
    const float* qkv_b  = (const float*)d_in[7];
    const float* proj_w = (const float*)d_in[8];
    const float* proj_b = (const float*)d_in[9];
    float* out = (float*)d_out;

    cudaMemcpyAsync(out + (size_t)PKE,     pk, (size_t)PKE * sizeof(float),
                    cudaMemcpyDeviceToDevice, 0);
    cudaMemcpyAsync(out + (size_t)2 * PKE, pv, (size_t)PKE * sizeof(float),
                    cudaMemcpyDeviceToDevice, 0);

    float *qbuf, *aobuf;
    __nv_bfloat16 *whp, *wlp;
    cudaGetSymbolAddress((void**)&qbuf, g_q);
    cudaGetSymbolAddress((void**)&aobuf, g_ao);
    cudaGetSymbolAddress((void**)&whp, g_wh);
    cudaGetSymbolAddress((void**)&wlp, g_wl);

    static bool attr_set = false;
    if (!attr_set) {
        cudaFuncSetAttribute(gemm_mma<0>, cudaFuncAttributeMaxDynamicSharedMemorySize, G_SMEM);
        cudaFuncSetAttribute(gemm_mma<1>, cudaFuncAttributeMaxDynamicSharedMemorySize, G_SMEM);
        attr_set = true;
    }

    conv_w_kernel<<<dim3(256, 2), 256>>>(qkv_w, proj_w);

    dim3 ggrid(4, 2048);   // N/128 x M/128
    gemm_mma<0><<<ggrid, 256, G_SMEM>>>(x, whp, wlp, qkv_b, qbuf);

    attn_kernel<<<32768, 256, 49152>>>(pk, pv, mask, table, rpi);

    gemm_mma<1><<<ggrid, 256, G_SMEM>>>(aobuf, whp + 262144, wlp + 262144, proj_b, out);
}

// round 5
// speedup vs baseline: 2.3695x; 1.3709x over previous
#include <cuda_runtime.h>
#include <cuda_bf16.h>
#include <cstdint>

#define PKE 134217728   // 4096*8*64*64

// Scratch (__device__ globals; allocation-free rule)
__device__ float g_q[PKE];                   // q in [B,H,N,64], pre-scaled
__device__ float g_ao[PKE];                  // attention out [B*N, 512] fp32
__device__ __nv_bfloat16 g_wh[2][262144];    // weight hi: [0]=qkv_w, [1]=proj_w
__device__ __nv_bfloat16 g_wl[2][262144];    // weight lo
__device__ float g_bias[32768];              // bias_full[h][i][j] = table[rpi[i][j]][h]

// ---------------------------------------------------------------------------
// helpers
// ---------------------------------------------------------------------------
__device__ __forceinline__ uint32_t smem_u32(const void* p) {
    uint32_t a;
    asm("{ .reg .u64 t; cvta.to.shared.u64 t, %1; cvt.u32.u64 %0, t; }"
        : "=r"(a) : "l"(p));
    return a;
}

__device__ __forceinline__ void ldsm_x4(uint32_t* d, uint32_t addr) {
    asm volatile("ldmatrix.sync.aligned.m8n8.x4.shared.b16 {%0,%1,%2,%3}, [%4];"
        : "=r"(d[0]), "=r"(d[1]), "=r"(d[2]), "=r"(d[3]) : "r"(addr));
}

__device__ __forceinline__ void ldsm_x4_t(uint32_t* d, uint32_t addr) {
    asm volatile("ldmatrix.sync.aligned.m8n8.x4.trans.shared.b16 {%0,%1,%2,%3}, [%4];"
        : "=r"(d[0]), "=r"(d[1]), "=r"(d[2]), "=r"(d[3]) : "r"(addr));
}

__device__ __forceinline__ void mma16816(float* c, const uint32_t* a,
                                         uint32_t b0, uint32_t b1) {
    asm volatile("mma.sync.aligned.m16n8k16.row.col.f32.bf16.bf16.f32 "
        "{%0,%1,%2,%3}, {%4,%5,%6,%7}, {%8,%9}, {%0,%1,%2,%3};"
        : "+f"(c[0]), "+f"(c[1]), "+f"(c[2]), "+f"(c[3])
        : "r"(a[0]), "r"(a[1]), "r"(a[2]), "r"(a[3]), "r"(b0), "r"(b1));
}

__device__ __forceinline__ uint32_t pack_bf2(float a, float b) {
    __nv_bfloat162 t = __floats2bfloat162_rn(a, b);
    return *reinterpret_cast<uint32_t*>(&t);
}

// split a float4 into bf16 hi (uint2) and lo (uint2)
__device__ __forceinline__ void split_f4(float4 v, uint2* hi, uint2* lo) {
    __nv_bfloat16 hx = __float2bfloat16(v.x), hy = __float2bfloat16(v.y);
    __nv_bfloat16 hz = __float2bfloat16(v.z), hw = __float2bfloat16(v.w);
    float lx = v.x - __bfloat162float(hx), ly = v.y - __bfloat162float(hy);
    float lz = v.z - __bfloat162float(hz), lw = v.w - __bfloat162float(hw);
    *hi = make_uint2(pack_bf2(__bfloat162float(hx), __bfloat162float(hy)),
                     pack_bf2(__bfloat162float(hz), __bfloat162float(hw)));
    *lo = make_uint2(pack_bf2(lx, ly), pack_bf2(lz, lw));
}

// ---------------------------------------------------------------------------
// Weight fp32 -> bf16 hi/lo split
// ---------------------------------------------------------------------------
__global__ void conv_w_kernel(const float* __restrict__ w0, const float* __restrict__ w1)
{
    int which = blockIdx.y;
    const float* src = which ? w1 : w0;
    int i = blockIdx.x * 256 + threadIdx.x;
    float4 v = ((const float4*)src)[i];
    uint2 h, l;
    split_f4(v, &h, &l);
    ((uint2*)g_wh[which])[i] = h;
    ((uint2*)g_wl[which])[i] = l;
}

// bias_full[h][i][j] = table[rpi[i*64+j]*8 + h]
__global__ void bias_kernel(const float* __restrict__ table, const int* __restrict__ rpi)
{
    int idx = blockIdx.x * 256 + threadIdx.x;   // 0..32767
    int h = idx >> 12, ij = idx & 4095;
    g_bias[idx] = table[rpi[ij] * 8 + h];
}

// ---------------------------------------------------------------------------
// mma.sync split-bf16 GEMM (unchanged from R4 passing version)
// ---------------------------------------------------------------------------
#define RP     80
#define AH_OFF 0
#define AL_OFF 10240
#define WH_OFF 20480
#define WL_OFF 30720
#define G_STAGE 40960
#define G_SMEM  (2 * G_STAGE)

template <int MODE>
__global__ void __launch_bounds__(256) gemm_mma(
    const float* __restrict__ A, const __nv_bfloat16* __restrict__ Wh,
    const __nv_bfloat16* __restrict__ Wl, const float* __restrict__ bias,
    float* __restrict__ C)
{
    extern __shared__ char smem[];
    const uint32_t sbase = smem_u32(smem);
    const int tid  = threadIdx.x;
    const int wid  = tid >> 5;
    const int lane = tid & 31;
    const int wr   = wid & 3;
    const int wn   = wid >> 2;
    const int n0   = blockIdx.x;
    const int m0   = blockIdx.y;

    const int L = lane;
    const uint32_t a_lrow = (L & 7) + ((L >> 3) & 1) * 8;
    const uint32_t a_lcol = ((L >> 4) & 1) * 16;
    const uint32_t b_lrow = (L & 7) + ((L >> 4) & 1) * 8;
    const uint32_t b_lcol = ((L >> 3) & 1) * 16;

    float acc[2][8][4];
#pragma unroll
    for (int mt = 0; mt < 2; mt++)
#pragma unroll
        for (int nt = 0; nt < 8; nt++)
#pragma unroll
            for (int q = 0; q < 4; q++) acc[mt][nt][q] = 0.f;

    float4 areg[4];
    uint4  whreg[2], wlreg[2];

#define LDG_CHUNK(kt)                                                          \
    {                                                                          \
        _Pragma("unroll")                                                      \
        for (int i = 0; i < 4; i++) {                                          \
            int cid = tid + i * 256;                                           \
            int r = cid >> 3, c4 = cid & 7;                                    \
            areg[i] = ((const float4*)A)[(size_t)(m0 * 128 + r) * 128 + (kt) * 8 + c4]; \
        }                                                                      \
        _Pragma("unroll")                                                      \
        for (int i = 0; i < 2; i++) {                                          \
            int cid = tid + i * 256;                                           \
            int r = cid >> 2, cu = cid & 3;                                    \
            size_t gi = (size_t)(n0 * 128 + r) * 64 + (kt) * 4 + cu;           \
            whreg[i] = ((const uint4*)Wh)[gi];                                 \
            wlreg[i] = ((const uint4*)Wl)[gi];                                 \
        }                                                                      \
    }

#define STS_CHUNK(buf)                                                         \
    {                                                                          \
        char* stg = smem + (buf) * G_STAGE;                                    \
        _Pragma("unroll")                                                      \
        for (int i = 0; i < 4; i++) {                                          \
            int cid = tid + i * 256;                                           \
            int r = cid >> 3, c4 = cid & 7;                                    \
            uint32_t off = r * RP + c4 * 8;                                    \
            uint2 h_, l_;                                                      \
            split_f4(areg[i], &h_, &l_);                                       \
            *(uint2*)(stg + AH_OFF + off) = h_;                                \
            *(uint2*)(stg + AL_OFF + off) = l_;                                \
        }                                                                      \
        _Pragma("unroll")                                                      \
        for (int i = 0; i < 2; i++) {                                          \
            int cid = tid + i * 256;                                           \
            int r = cid >> 2, cu = cid & 3;                                    \
            uint32_t off = r * RP + cu * 16;                                   \
            *(uint4*)(stg + WH_OFF + off) = whreg[i];                          \
            *(uint4*)(stg + WL_OFF + off) = wlreg[i];                          \
        }                                                                      \
    }

    LDG_CHUNK(0);
    STS_CHUNK(0);
    LDG_CHUNK(1);
    __syncthreads();

    for (int kt = 0; kt < 16; kt++) {
        const int b = kt & 1;
        if (kt < 15) STS_CHUNK(1 - b);
        if (kt < 14) LDG_CHUNK(kt + 2);
        __syncthreads();

        const uint32_t stg = sbase + b * G_STAGE;
#pragma unroll
        for (int s = 0; s < 2; s++) {
            uint32_t ah[2][4], al[2][4];
#pragma unroll
            for (int mt = 0; mt < 2; mt++) {
                uint32_t ro = (wr * 32 + mt * 16 + a_lrow) * RP + s * 32 + a_lcol;
                ldsm_x4(ah[mt], stg + AH_OFF + ro);
                ldsm_x4(al[mt], stg + AL_OFF + ro);
            }
#pragma unroll
            for (int g = 0; g < 4; g++) {
                uint32_t bh[4], bl[4];
                uint32_t ro = (wn * 64 + g * 16 + b_lrow) * RP + s * 32 + b_lcol;
                ldsm_x4(bh, stg + WH_OFF + ro);
                ldsm_x4(bl, stg + WL_OFF + ro);
#pragma unroll
                for (int mt = 0; mt < 2; mt++) {
                    mma16816(acc[mt][2 * g],     ah[mt], bh[0], bh[1]);
                    mma16816(acc[mt][2 * g + 1], ah[mt], bh[2], bh[3]);
                    mma16816(acc[mt][2 * g],     al[mt], bh[0], bh[1]);
                    mma16816(acc[mt][2 * g + 1], al[mt], bh[2], bh[3]);
                    mma16816(acc[mt][2 * g],     ah[mt], bl[0], bl[1]);
                    mma16816(acc[mt][2 * g + 1], ah[mt], bl[2], bl[3]);
                }
            }
        }
        __syncthreads();
    }

    const int g_  = lane >> 2;
    const int tig = lane & 3;
#pragma unroll
    for (int mt = 0; mt < 2; mt++) {
        const int mbase = m0 * 128 + wr * 32 + mt * 16 + g_;
#pragma unroll
        for (int nt = 0; nt < 8; nt++) {
            const int j = n0 * 128 + wn * 64 + nt * 8 + tig * 2;
            const float bx = __ldg(bias + j), by = __ldg(bias + j + 1);
#pragma unroll
            for (int half = 0; half < 2; half++) {
                const int m = mbase + half * 8;
                float ox = acc[mt][nt][2 * half]     + bx;
                float oy = acc[mt][nt][2 * half + 1] + by;
                float* dst;
                if (MODE == 0) {
                    ox *= 0.125f; oy *= 0.125f;
                    int b_i = m >> 6, n_i = m & 63;
                    int h_i = j >> 6, d_i = j & 63;
                    dst = C + (((size_t)(b_i * 8 + h_i)) << 12) + (n_i << 6) + d_i;
                } else {
                    dst = C + (size_t)m * 512 + j;
                }
                *(float2*)dst = make_float2(ox, oy);
            }
        }
    }
#undef LDG_CHUNK
#undef STS_CHUNK
}

// ---------------------------------------------------------------------------
// Attention via mma.sync split-bf16. One block per (b, h), 128 threads.
// 4 warps x m16 row stripes, n=64 full width per warp -> warp-local softmax.
// Also fuses the p_k / p_v pass-through copies.
// smem: Qh Ql Kh Kl Vh Vl, 64 rows x 72 bf16 (144B pitch) each = 55296 B.
// ---------------------------------------------------------------------------
#define AP 144                 // smem row pitch (bytes)
#define QH_O 0
#define QL_O 9216
#define KH_O 18432
#define KL_O 27648
#define VH_O 36864
#define VL_O 46080
#define A_SMEM 55296

__global__ void __launch_bounds__(128) attn_mma(
    const float* __restrict__ pk, const float* __restrict__ pv,
    const float* __restrict__ mask,
    float* __restrict__ out_k, float* __restrict__ out_v)
{
    extern __shared__ char smem[];
    const uint32_t sb = smem_u32(smem);
    const int tid = threadIdx.x;
    const int wid = tid >> 5;
    const int lane = tid & 31;
    const int bh = blockIdx.x;
    const int b = bh >> 3, h = bh & 7;
    const int w = b & 255;

    // ---- load + split + pass-through ----
    const float4* qg = (const float4*)(g_q + (size_t)bh * 4096);
    const float4* kg = (const float4*)(pk + (size_t)bh * 4096);
    const float4* vg = (const float4*)(pv + (size_t)bh * 4096);
    float4* ok = (float4*)(out_k + (size_t)bh * 4096);
    float4* ov = (float4*)(out_v + (size_t)bh * 4096);

#pragma unroll
    for (int i = 0; i < 8; i++) {
        int idx = tid + i * 128;            // 0..1023 float4s
        int r = idx >> 4, c = idx & 15;
        uint32_t off = r * AP + c * 8;
        uint2 hi, lo;
        float4 q4 = qg[idx];
        split_f4(q4, &hi, &lo);
        *(uint2*)(smem + QH_O + off) = hi;
        *(uint2*)(smem + QL_O + off) = lo;
        float4 k4 = kg[idx];
        ok[idx] = k4;
        split_f4(k4, &hi, &lo);
        *(uint2*)(smem + KH_O + off) = hi;
        *(uint2*)(smem + KL_O + off) = lo;
        float4 v4 = vg[idx];
        ov[idx] = v4;
        split_f4(v4, &hi, &lo);
        *(uint2*)(smem + VH_O + off) = hi;
        *(uint2*)(smem + VL_O + off) = lo;
    }
    __syncthreads();

    // ldmatrix address components
    const uint32_t aQ = sb + QH_O + (wid * 16 + (lane & 15)) * AP + ((lane >> 4) << 4);
    const uint32_t aK = sb + KH_O + ((lane & 7) + ((lane >> 4) << 3)) * AP
                                  + (((lane >> 3) & 1) << 4);
    const uint32_t aV = sb + VH_O + ((lane & 7) + (((lane >> 3) & 1) << 3)) * AP
                                  + ((lane >> 4) << 4);

    // ---- S = Q K^T (3-product split) ----
    float sacc[8][4];
#pragma unroll
    for (int nt = 0; nt < 8; nt++)
#pragma unroll
        for (int q = 0; q < 4; q++) sacc[nt][q] = 0.f;

#pragma unroll
    for (int ks = 0; ks < 4; ks++) {
        uint32_t ahf[4], alf[4];
        ldsm_x4(ahf, aQ + ks * 32);
        ldsm_x4(alf, aQ + (QL_O - QH_O) + ks * 32);
#pragma unroll
        for (int jb = 0; jb < 4; jb++) {
            uint32_t kh[4], kl[4];
            uint32_t ro = jb * 16 * AP + ks * 32;
            ldsm_x4(kh, aK + ro);
            ldsm_x4(kl, aK + (KL_O - KH_O) + ro);
            mma16816(sacc[2 * jb],     ahf, kh[0], kh[1]);
            mma16816(sacc[2 * jb + 1], ahf, kh[2], kh[3]);
            mma16816(sacc[2 * jb],     alf, kh[0], kh[1]);
            mma16816(sacc[2 * jb + 1], alf, kh[2], kh[3]);
            mma16816(sacc[2 * jb],     ahf, kl[0], kl[1]);
            mma16816(sacc[2 * jb + 1], ahf, kl[2], kl[3]);
        }
    }

    // ---- bias + mask + softmax (warp-local rows) ----
    const int g_ = lane >> 2, t4 = lane & 3;
    const int i0 = wid * 16 + g_;     // row g
    const int i1 = i0 + 8;            // row g+8
    const float* mrow0 = mask + (size_t)w * 4096 + i0 * 64;
    const float* mrow1 = mask + (size_t)w * 4096 + i1 * 64;
    const float* brow0 = g_bias + h * 4096 + i0 * 64;
    const float* brow1 = g_bias + h * 4096 + i1 * 64;

#pragma unroll
    for (int nt = 0; nt < 8; nt++) {
        int j = nt * 8 + t4 * 2;
        float2 m0 = *(const float2*)(mrow0 + j);
        float2 b0 = *(const float2*)(brow0 + j);
        float2 m1 = *(const float2*)(mrow1 + j);
        float2 b1 = *(const float2*)(brow1 + j);
        sacc[nt][0] += m0.x + b0.x;
        sacc[nt][1] += m0.y + b0.y;
        sacc[nt][2] += m1.x + b1.x;
        sacc[nt][3] += m1.y + b1.y;
    }

    float mx0 = -1e30f, mx1 = -1e30f;
#pragma unroll
    for (int nt = 0; nt < 8; nt++) {
        mx0 = fmaxf(mx0, fmaxf(sacc[nt][0], sacc[nt][1]));
        mx1 = fmaxf(mx1, fmaxf(sacc[nt][2], sacc[nt][3]));
    }
    mx0 = fmaxf(mx0, __shfl_xor_sync(0xffffffffu, mx0, 1));
    mx0 = fmaxf(mx0, __shfl_xor_sync(0xffffffffu, mx0, 2));
    mx1 = fmaxf(mx1, __shfl_xor_sync(0xffffffffu, mx1, 1));
    mx1 = fmaxf(mx1, __shfl_xor_sync(0xffffffffu, mx1, 2));

    float s0 = 0.f, s1 = 0.f;
#pragma unroll
    for (int nt = 0; nt < 8; nt++) {
        sacc[nt][0] = __expf(sacc[nt][0] - mx0);
        sacc[nt][1] = __expf(sacc[nt][1] - mx0);
        sacc[nt][2] = __expf(sacc[nt][2] - mx1);
        sacc[nt][3] = __expf(sacc[nt][3] - mx1);
        s0 += sacc[nt][0] + sacc[nt][1];
        s1 += sacc[nt][2] + sacc[nt][3];
    }
    s0 += __shfl_xor_sync(0xffffffffu, s0, 1);
    s0 += __shfl_xor_sync(0xffffffffu, s0, 2);
    s1 += __shfl_xor_sync(0xffffffffu, s1, 1);
    s1 += __shfl_xor_sync(0xffffffffu, s1, 2);
    const float inv0 = 1.0f / s0, inv1 = 1.0f / s1;

    // ---- P -> bf16 hi/lo fragments (registers only) ----
    uint32_t phi0[8], plo0[8], phi1[8], plo1[8];
#pragma unroll
    for (int nt = 0; nt < 8; nt++) {
        float p0 = sacc[nt][0] * inv0, p1 = sacc[nt][1] * inv0;
        float p2 = sacc[nt][2] * inv1, p3 = sacc[nt][3] * inv1;
        __nv_bfloat16 h0 = __float2bfloat16(p0), h1 = __float2bfloat16(p1);
        __nv_bfloat16 h2 = __float2bfloat16(p2), h3 = __float2bfloat16(p3);
        phi0[nt] = pack_bf2(__bfloat162float(h0), __bfloat162float(h1));
        phi1[nt] = pack_bf2(__bfloat162float(h2), __bfloat162float(h3));
        plo0[nt] = pack_bf2(p0 - __bfloat162float(h0), p1 - __bfloat162float(h1));
        plo1[nt] = pack_bf2(p2 - __bfloat162float(h2), p3 - __bfloat162float(h3));
    }

    // ---- O = P V (3-product split), V frags via ldmatrix.trans ----
    float oacc[8][4];
#pragma unroll
    for (int nt = 0; nt < 8; nt++)
#pragma unroll
        for (int q = 0; q < 4; q++) oacc[nt][q] = 0.f;

#pragma unroll
    for (int ks = 0; ks < 4; ks++) {
        uint32_t pa[4] = {phi0[2 * ks], phi1[2 * ks], phi0[2 * ks + 1], phi1[2 * ks + 1]};
        uint32_t pb[4] = {plo0[2 * ks], plo1[2 * ks], plo0[2 * ks + 1], plo1[2 * ks + 1]};
#pragma unroll
        for (int db = 0; db < 4; db++) {
            uint32_t vh[4], vl[4];
            uint32_t ro = ks * 16 * AP + db * 32;
            ldsm_x4_t(vh, aV + ro);
            ldsm_x4_t(vl, aV + (VL_O - VH_O) + ro);
            mma16816(oacc[2 * db],     pa, vh[0], vh[1]);
            mma16816(oacc[2 * db + 1], pa, vh[2], vh[3]);
            mma16816(oacc[2 * db],     pb, vh[0], vh[1]);
            mma16816(oacc[2 * db + 1], pb, vh[2], vh[3]);
            mma16816(oacc[2 * db],     pa, vl[0], vl[1]);
            mma16816(oacc[2 * db + 1], pa, vl[2], vl[3]);
        }
    }

    // ---- write O to g_ao [b*64 + i][h*64 + d] ----
    float* og0 = g_ao + ((size_t)(b * 64 + i0)) * 512 + h * 64;
    float* og1 = g_ao + ((size_t)(b * 64 + i1)) * 512 + h * 64;
#pragma unroll
    for (int nt = 0; nt < 8; nt++) {
        int d = nt * 8 + t4 * 2;
        *(float2*)(og0 + d) = make_float2(oacc[nt][0], oacc[nt][1]);
        *(float2*)(og1 + d) = make_float2(oacc[nt][2], oacc[nt][3]);
    }
}

// ---------------------------------------------------------------------------
extern "C" void kernel_launch(void* const* d_in, const int* in_sizes, int n_in,
                              void* d_out, int out_size)
{
    const float* x      = (const float*)d_in[0];
    const float* pk     = (const float*)d_in[1];
    const float* pv     = (const float*)d_in[2];
    const float* mask   = (const float*)d_in[3];
    const float* table  = (const float*)d_in[4];
    const int*   rpi    = (const int*)d_in[5];
    const float* qkv_w  = (const float*)d_in[6];
    const float* qkv_b  = (const float*)d_in[7];
    const float* proj_w = (const float*)d_in[8];
    const float* proj_b = (const float*)d_in[9];
    float* out = (float*)d_out;

    float *qbuf, *aobuf;
    __nv_bfloat16 *whp, *wlp;
    cudaGetSymbolAddress((void**)&qbuf, g_q);
    cudaGetSymbolAddress((void**)&aobuf, g_ao);
    cudaGetSymbolAddress((void**)&whp, g_wh);
    cudaGetSymbolAddress((void**)&wlp, g_wl);

    static bool attr_set = false;
    if (!attr_set) {
        cudaFuncSetAttribute(gemm_mma<0>, cudaFuncAttributeMaxDynamicSharedMemorySize, G_SMEM);
        cudaFuncSetAttribute(gemm_mma<1>, cudaFuncAttributeMaxDynamicSharedMemorySize, G_SMEM);
        cudaFuncSetAttribute(attn_mma,    cudaFuncAttributeMaxDynamicSharedMemorySize, A_SMEM);
        attr_set = true;
    }

    conv_w_kernel<<<dim3(256, 2), 256>>>(qkv_w, proj_w);
    bias_kernel<<<128, 256>>>(table, rpi);

    dim3 ggrid(4, 2048);   // N/128 x M/128
    gemm_mma<0><<<ggrid, 256, G_SMEM>>>(x, whp, wlp, qkv_b, qbuf);

    attn_mma<<<32768, 128, A_SMEM>>>(pk, pv, mask, out + (size_t)PKE,
                                     out + (size_t)2 * PKE);

    gemm_mma<1><<<ggrid, 256, G_SMEM>>>(aobuf, whp + 262144, wlp + 262144, proj_b, out);
}